// round 1
// baseline (speedup 1.0000x reference)
#include <cuda_runtime.h>
#include <math.h>

#define N 8192
#define D 1024
#define BM 64
#define BN 64
#define BK 16

// Scratch (allocation-free rule: __device__ globals)
__device__ float g_xn[(size_t)N * D];   // normalized rows, 32 MB
__device__ float g_top[N];
__device__ float g_bot[N];
__device__ int   g_lab[N];

// ---------------------------------------------------------------------------
// Row normalization: xn = x / max(||x||, 1e-8). Also zero top/bot accumulators.
// One block (256 threads) per row; each thread owns one float4 (D=1024).
// ---------------------------------------------------------------------------
__global__ void normalize_kernel(const float* __restrict__ x) {
    int row = blockIdx.x;
    int t = threadIdx.x;
    const float4* xr = reinterpret_cast<const float4*>(x + (size_t)row * D);
    float4 v = xr[t];
    float ss = v.x * v.x + v.y * v.y + v.z * v.z + v.w * v.w;
    #pragma unroll
    for (int o = 16; o; o >>= 1) ss += __shfl_xor_sync(0xffffffffu, ss, o);
    __shared__ float sred[8];
    int lane = t & 31, w = t >> 5;
    if (lane == 0) sred[w] = ss;
    __syncthreads();
    if (t < 32) {
        float s2 = (t < 8) ? sred[t] : 0.0f;
        #pragma unroll
        for (int o = 4; o; o >>= 1) s2 += __shfl_xor_sync(0xffffffffu, s2, o);
        if (t == 0) sred[0] = s2;
    }
    __syncthreads();
    float inv = 1.0f / fmaxf(sqrtf(sred[0]), 1e-8f);
    float4 o4 = make_float4(v.x * inv, v.y * inv, v.z * inv, v.w * inv);
    reinterpret_cast<float4*>(g_xn + (size_t)row * D)[t] = o4;
    if (t == 0) { g_top[row] = 0.0f; g_bot[row] = 0.0f; }
}

// ---------------------------------------------------------------------------
// Label conversion with int64/int32 layout auto-detection.
// Labels are in [0,10). If the buffer is little-endian int64, every odd int32
// word is 0. 256 random int32 labels being all zero has prob 1e-256, so:
// all-zero odd words  => int64 layout; otherwise int32 layout.
// ---------------------------------------------------------------------------
__global__ void labels_kernel(const int* __restrict__ y32) {
    __shared__ int odd_nonzero;
    int t = threadIdx.x;
    if (t == 0) odd_nonzero = 0;
    __syncthreads();
    if (t < 256 && y32[2 * t + 1] != 0) odd_nonzero = 1;  // race-benign
    __syncthreads();
    bool is64 = (odd_nonzero == 0);
    int i = blockIdx.x * blockDim.x + t;
    if (i < N) g_lab[i] = is64 ? y32[2 * i] : y32[i];
}

// ---------------------------------------------------------------------------
// Fused sim-GEMM + SNNL epilogue.
// Block = 256 threads, computes a BM x BN tile of sim = xn @ xn^T via shared
// tiles over K=D. Epilogue applies f = exp((sim-1)/T), masks diagonal,
// accumulates per-row top (same-label) and bot (off-diag) partial sums,
// reduces across the 16 tx lanes via shuffle, atomicAdds into g_top/g_bot.
// ---------------------------------------------------------------------------
__global__ void __launch_bounds__(256, 2)
snnl_main(const float* __restrict__ Tptr) {
    __shared__ float As[BK][BM];
    __shared__ float Bs[BK][BN];
    __shared__ int   yj_s[BN];

    int i0 = blockIdx.y * BM;
    int j0 = blockIdx.x * BN;
    int tid = threadIdx.x;
    int tx = tid & 15;        // 0..15 -> j micro index
    int ty = tid >> 4;        // 0..15 -> i micro index
    int lrow = tid >> 2;      // 0..63 load row
    int lcol = (tid & 3) << 2;// 0,4,8,12 load col (float4)

    const float* Abase = g_xn + (size_t)(i0 + lrow) * D + lcol;
    const float* Bbase = g_xn + (size_t)(j0 + lrow) * D + lcol;

    if (tid < BN) yj_s[tid] = g_lab[j0 + tid];

    float acc[4][4];
    #pragma unroll
    for (int a = 0; a < 4; a++)
        #pragma unroll
        for (int b = 0; b < 4; b++) acc[a][b] = 0.0f;

    for (int k0 = 0; k0 < D; k0 += BK) {
        float4 a4 = *reinterpret_cast<const float4*>(Abase + k0);
        float4 b4 = *reinterpret_cast<const float4*>(Bbase + k0);
        __syncthreads();   // previous compute done before overwriting tiles
        As[lcol + 0][lrow] = a4.x;
        As[lcol + 1][lrow] = a4.y;
        As[lcol + 2][lrow] = a4.z;
        As[lcol + 3][lrow] = a4.w;
        Bs[lcol + 0][lrow] = b4.x;
        Bs[lcol + 1][lrow] = b4.y;
        Bs[lcol + 2][lrow] = b4.z;
        Bs[lcol + 3][lrow] = b4.w;
        __syncthreads();
        #pragma unroll
        for (int k = 0; k < BK; k++) {
            float af[4], bf[4];
            #pragma unroll
            for (int ii = 0; ii < 4; ii++) af[ii] = As[k][(ty << 2) + ii];
            #pragma unroll
            for (int jj = 0; jj < 4; jj++) bf[jj] = Bs[k][(tx << 2) + jj];
            #pragma unroll
            for (int ii = 0; ii < 4; ii++)
                #pragma unroll
                for (int jj = 0; jj < 4; jj++)
                    acc[ii][jj] = fmaf(af[ii], bf[jj], acc[ii][jj]);
        }
    }

    // Epilogue
    float invT = 1.0f / Tptr[0];
    int yi[4];
    #pragma unroll
    for (int ii = 0; ii < 4; ii++) yi[ii] = g_lab[i0 + (ty << 2) + ii];

    #pragma unroll
    for (int ii = 0; ii < 4; ii++) {
        int i = i0 + (ty << 2) + ii;
        float ts = 0.0f, bs = 0.0f;
        #pragma unroll
        for (int jj = 0; jj < 4; jj++) {
            int j = j0 + (tx << 2) + jj;
            float f = __expf((acc[ii][jj] - 1.0f) * invT);
            if (i == j) f = 0.0f;          // off-diagonal mask
            bs += f;
            if (yi[ii] == yj_s[(tx << 2) + jj]) ts += f;  // diag already zeroed
        }
        // reduce over the 16 tx lanes (contiguous lanes within half-warp)
        #pragma unroll
        for (int o = 1; o < 16; o <<= 1) {
            ts += __shfl_xor_sync(0xffffffffu, ts, o);
            bs += __shfl_xor_sync(0xffffffffu, bs, o);
        }
        if (tx == 0) {
            atomicAdd(&g_top[i], ts);
            atomicAdd(&g_bot[i], bs);
        }
    }
}

// ---------------------------------------------------------------------------
// Final loss: -mean(log((top + 1e-9) / bot))
// ---------------------------------------------------------------------------
__global__ void loss_kernel(float* __restrict__ out) {
    int t = threadIdx.x;
    float s = 0.0f;
    for (int i = t; i < N; i += 256)
        s += logf((g_top[i] + 1e-9f) / g_bot[i]);
    #pragma unroll
    for (int o = 16; o; o >>= 1) s += __shfl_xor_sync(0xffffffffu, s, o);
    __shared__ float sred[8];
    int lane = t & 31, w = t >> 5;
    if (lane == 0) sred[w] = s;
    __syncthreads();
    if (t < 32) {
        float s2 = (t < 8) ? sred[t] : 0.0f;
        #pragma unroll
        for (int o = 4; o; o >>= 1) s2 += __shfl_xor_sync(0xffffffffu, s2, o);
        if (t == 0) out[0] = -s2 / (float)N;
    }
}

extern "C" void kernel_launch(void* const* d_in, const int* in_sizes, int n_in,
                              void* d_out, int out_size) {
    const float* x = (const float*)d_in[0];
    const int*   y = (const int*)d_in[1];   // int32 view; layout auto-detected
    const float* T = (const float*)d_in[2];
    float* out = (float*)d_out;

    normalize_kernel<<<N, 256>>>(x);
    labels_kernel<<<N / 256, 256>>>(y);
    snnl_main<<<dim3(N / BN, N / BM), 256>>>(T);
    loss_kernel<<<1, 256>>>(out);
}

// round 3
// speedup vs baseline: 10.6381x; 10.6381x over previous
#include <cuda_runtime.h>
#include <cuda_bf16.h>
#include <math.h>
#include <stdint.h>

#define N 8192
#define D 1024
#define BM 128
#define BN 128
#define BK 32
#define KSTEPS (D / BK)   // 32

// Scratch (__device__ globals: allocation-free rule)
__device__ __nv_bfloat16 g_xnb[(size_t)N * D];   // normalized rows, bf16, 16 MB
__device__ float g_top[N];
__device__ float g_bot[N];
__device__ int   g_lab[N];

// ------------------------------ PTX helpers -------------------------------
__device__ __forceinline__ uint32_t smem_u32(const void* p) {
    uint32_t a;
    asm("{ .reg .u64 t; cvta.to.shared.u64 t, %1; cvt.u32.u64 %0, t; }"
        : "=r"(a) : "l"(p));
    return a;
}
#define CPA(dst, src) \
    asm volatile("cp.async.cg.shared.global [%0], [%1], 16;" :: "r"(dst), "l"(src) : "memory")
#define CPA_COMMIT() asm volatile("cp.async.commit_group;" ::: "memory")
#define CPA_WAIT0()  asm volatile("cp.async.wait_group 0;" ::: "memory")
#define CPA_WAIT1()  asm volatile("cp.async.wait_group 1;" ::: "memory")

#define LDX4(r, a) \
    asm volatile("ldmatrix.sync.aligned.m8n8.x4.shared.b16 {%0,%1,%2,%3}, [%4];" \
        : "=r"((r)[0]), "=r"((r)[1]), "=r"((r)[2]), "=r"((r)[3]) : "r"(a))

__device__ __forceinline__ void mma16816(float* d, const uint32_t* a, const uint32_t* b) {
    asm volatile(
        "mma.sync.aligned.m16n8k16.row.col.f32.bf16.bf16.f32 "
        "{%0,%1,%2,%3}, {%4,%5,%6,%7}, {%8,%9}, {%0,%1,%2,%3};"
        : "+f"(d[0]), "+f"(d[1]), "+f"(d[2]), "+f"(d[3])
        : "r"(a[0]), "r"(a[1]), "r"(a[2]), "r"(a[3]), "r"(b[0]), "r"(b[1]));
}

// ---------------------------------------------------------------------------
// Row normalization -> bf16 unit rows; zero top/bot accumulators.
// ---------------------------------------------------------------------------
__global__ void normalize_kernel(const float* __restrict__ x) {
    int row = blockIdx.x;
    int t = threadIdx.x;
    const float4* xr = reinterpret_cast<const float4*>(x + (size_t)row * D);
    float4 v = xr[t];
    float ss = v.x * v.x + v.y * v.y + v.z * v.z + v.w * v.w;
    #pragma unroll
    for (int o = 16; o; o >>= 1) ss += __shfl_xor_sync(0xffffffffu, ss, o);
    __shared__ float sred[8];
    int lane = t & 31, w = t >> 5;
    if (lane == 0) sred[w] = ss;
    __syncthreads();
    if (t < 32) {
        float s2 = (t < 8) ? sred[t] : 0.0f;
        #pragma unroll
        for (int o = 4; o; o >>= 1) s2 += __shfl_xor_sync(0xffffffffu, s2, o);
        if (t == 0) sred[0] = s2;
    }
    __syncthreads();
    float inv = 1.0f / fmaxf(sqrtf(sred[0]), 1e-8f);
    __nv_bfloat162* dst = reinterpret_cast<__nv_bfloat162*>(g_xnb + (size_t)row * D);
    dst[2 * t + 0] = __floats2bfloat162_rn(v.x * inv, v.y * inv);
    dst[2 * t + 1] = __floats2bfloat162_rn(v.z * inv, v.w * inv);
    if (t == 0) { g_top[row] = 0.0f; g_bot[row] = 0.0f; }
}

// ---------------------------------------------------------------------------
// Label conversion with int64/int32 auto-detection (labels in [0,10)).
// ---------------------------------------------------------------------------
__global__ void labels_kernel(const int* __restrict__ y32) {
    __shared__ int odd_nonzero;
    int t = threadIdx.x;
    if (t == 0) odd_nonzero = 0;
    __syncthreads();
    if (t < 256 && y32[2 * t + 1] != 0) odd_nonzero = 1;
    __syncthreads();
    bool is64 = (odd_nonzero == 0);
    int i = blockIdx.x * blockDim.x + t;
    if (i < N) g_lab[i] = is64 ? y32[2 * i] : y32[i];
}

// ---------------------------------------------------------------------------
// HMMA fused sim-GEMM + SNNL epilogue. 256 threads (8 warps: 2 M x 4 N).
// smem: double-buffered A/B tiles, 64B rows, 16B-chunk XOR swizzle.
// ---------------------------------------------------------------------------
__global__ void __launch_bounds__(256, 2)
snnl_hmma(const float* __restrict__ Tptr) {
    __shared__ __align__(1024) __nv_bfloat16 sA[2][BM * BK];
    __shared__ __align__(1024) __nv_bfloat16 sB[2][BN * BK];

    const int tid = threadIdx.x;
    const int wid = tid >> 5;
    const int lane = tid & 31;
    const int i0 = blockIdx.y * BM;
    const int j0 = blockIdx.x * BN;
    const int wm = (wid >> 2) * 64;   // 0 / 64
    const int wn = (wid & 3) * 32;    // 0 / 32 / 64 / 96

    uint32_t aBase[2] = { smem_u32(&sA[0][0]), smem_u32(&sA[1][0]) };
    uint32_t bBase[2] = { smem_u32(&sB[0][0]), smem_u32(&sB[1][0]) };

    // --- loader mapping: 256 threads cover 64 rows x 4 x 16B chunks; two halves
    const int lrow = tid >> 2;        // 0..63
    const int lch  = tid & 3;         // 16B chunk in 64B row
    const uint32_t loff = lrow * 64 + ((lch ^ ((lrow >> 1) & 3)) << 4);
    const __nv_bfloat16* Ag = g_xnb + (size_t)(i0 + lrow) * D + lch * 8;
    const __nv_bfloat16* Bg = g_xnb + (size_t)(j0 + lrow) * D + lch * 8;
    // rows +64 have identical swizzle term -> offset +4096 bytes

    // --- ldmatrix per-lane address components
    // A tile mt: rows wm+mt*16 .. +15 ; matrices: [rows0-7,k0-7][rows8-15,k0-7][rows0-7,k8-15][rows8-15,k8-15]
    uint32_t aoff[4], asw[4];
    #pragma unroll
    for (int mt = 0; mt < 4; mt++) {
        int r = wm + mt * 16 + ((lane >> 3) & 1) * 8 + (lane & 7);
        aoff[mt] = r * 64;
        asw[mt] = (r >> 1) & 3;
    }
    // B tile bt covers 16 n-cols: matrices: [n0-7,k0-7][n0-7,k8-15][n8-15,k0-7][n8-15,k8-15]
    uint32_t boff[2], bsw[2];
    #pragma unroll
    for (int bt = 0; bt < 2; bt++) {
        int r = wn + bt * 16 + (lane >> 4) * 8 + (lane & 7);
        boff[bt] = r * 64;
        bsw[bt] = (r >> 1) & 3;
    }

    float acc[4][4][4];
    #pragma unroll
    for (int a = 0; a < 4; a++)
        #pragma unroll
        for (int b = 0; b < 4; b++)
            #pragma unroll
            for (int c = 0; c < 4; c++) acc[a][b][c] = 0.0f;

    // prologue: load chunk 0 into buffer 0
    CPA(aBase[0] + loff,        Ag);
    CPA(aBase[0] + loff + 4096, Ag + (size_t)64 * D);
    CPA(bBase[0] + loff,        Bg);
    CPA(bBase[0] + loff + 4096, Bg + (size_t)64 * D);
    CPA_COMMIT();

    for (int kc = 0; kc < KSTEPS; kc++) {
        const int b = kc & 1;
        if (kc + 1 < KSTEPS) {
            const __nv_bfloat16* An = Ag + (kc + 1) * BK;
            const __nv_bfloat16* Bn = Bg + (kc + 1) * BK;
            CPA(aBase[1 - b] + loff,        An);
            CPA(aBase[1 - b] + loff + 4096, An + (size_t)64 * D);
            CPA(bBase[1 - b] + loff,        Bn);
            CPA(bBase[1 - b] + loff + 4096, Bn + (size_t)64 * D);
            CPA_COMMIT();
            CPA_WAIT1();
        } else {
            CPA_WAIT0();
        }
        __syncthreads();

        #pragma unroll
        for (int ks = 0; ks < 2; ks++) {
            uint32_t af[4][4], bf[2][4];
            const uint32_t ca = 2 * ks + (lane >> 4);          // A chunk
            const uint32_t cb = 2 * ks + ((lane >> 3) & 1);    // B chunk
            #pragma unroll
            for (int mt = 0; mt < 4; mt++)
                LDX4(af[mt], aBase[b] + aoff[mt] + ((ca ^ asw[mt]) << 4));
            #pragma unroll
            for (int bt = 0; bt < 2; bt++)
                LDX4(bf[bt], bBase[b] + boff[bt] + ((cb ^ bsw[bt]) << 4));
            #pragma unroll
            for (int mt = 0; mt < 4; mt++)
                #pragma unroll
                for (int nt = 0; nt < 4; nt++)
                    mma16816(acc[mt][nt], af[mt], &bf[nt >> 1][(nt & 1) * 2]);
        }
        __syncthreads();
    }

    // ---------------- epilogue ----------------
    const float invT = 1.0f / Tptr[0];
    float* rowsum = reinterpret_cast<float*>(&sA[0][0]);   // 128 rows x {top,bot}
    rowsum[tid] = 0.0f;                                     // 256 floats
    __syncthreads();

    const int g = lane >> 2, tig = lane & 3;
    int yj[4][2];
    #pragma unroll
    for (int nt = 0; nt < 4; nt++) {
        int j = j0 + wn + nt * 8 + 2 * tig;
        yj[nt][0] = g_lab[j];
        yj[nt][1] = g_lab[j + 1];
    }

    #pragma unroll
    for (int mt = 0; mt < 4; mt++) {
        #pragma unroll
        for (int h = 0; h < 2; h++) {
            const int li = wm + mt * 16 + h * 8 + g;
            const int i = i0 + li;
            const int yi = g_lab[i];
            float ts = 0.0f, bs = 0.0f;
            #pragma unroll
            for (int nt = 0; nt < 4; nt++) {
                float d0 = acc[mt][nt][h * 2 + 0];
                float d1 = acc[mt][nt][h * 2 + 1];
                int j = j0 + wn + nt * 8 + 2 * tig;
                float f0 = __expf((d0 - 1.0f) * invT);
                float f1 = __expf((d1 - 1.0f) * invT);
                if (i == j) f0 = 0.0f;
                if (i == j + 1) f1 = 0.0f;
                bs += f0 + f1;
                if (yi == yj[nt][0]) ts += f0;
                if (yi == yj[nt][1]) ts += f1;
            }
            ts += __shfl_xor_sync(0xffffffffu, ts, 1);
            ts += __shfl_xor_sync(0xffffffffu, ts, 2);
            bs += __shfl_xor_sync(0xffffffffu, bs, 1);
            bs += __shfl_xor_sync(0xffffffffu, bs, 2);
            if (tig == 0) {
                atomicAdd(&rowsum[li * 2 + 0], ts);
                atomicAdd(&rowsum[li * 2 + 1], bs);
            }
        }
    }
    __syncthreads();
    if (tid < BM) {
        atomicAdd(&g_top[i0 + tid], rowsum[tid * 2 + 0]);
        atomicAdd(&g_bot[i0 + tid], rowsum[tid * 2 + 1]);
    }
}

// ---------------------------------------------------------------------------
// Final loss: -mean(log((top + 1e-9) / bot))
// ---------------------------------------------------------------------------
__global__ void loss_kernel(float* __restrict__ out) {
    int t = threadIdx.x;
    float s = 0.0f;
    for (int i = t; i < N; i += 256)
        s += logf((g_top[i] + 1e-9f) / g_bot[i]);
    #pragma unroll
    for (int o = 16; o; o >>= 1) s += __shfl_xor_sync(0xffffffffu, s, o);
    __shared__ float sred[8];
    int lane = t & 31, w = t >> 5;
    if (lane == 0) sred[w] = s;
    __syncthreads();
    if (t < 32) {
        float s2 = (t < 8) ? sred[t] : 0.0f;
        #pragma unroll
        for (int o = 4; o; o >>= 1) s2 += __shfl_xor_sync(0xffffffffu, s2, o);
        if (t == 0) out[0] = -s2 / (float)N;
    }
}

extern "C" void kernel_launch(void* const* d_in, const int* in_sizes, int n_in,
                              void* d_out, int out_size) {
    const float* x = (const float*)d_in[0];
    const int*   y = (const int*)d_in[1];   // int32 view; layout auto-detected
    const float* T = (const float*)d_in[2];
    float* out = (float*)d_out;

    normalize_kernel<<<N, 256>>>(x);
    labels_kernel<<<N / 256, 256>>>(y);
    snnl_hmma<<<dim3(N / BN, N / BM), 256>>>(T);
    loss_kernel<<<1, 256>>>(out);
}

// round 4
// speedup vs baseline: 18.1714x; 1.7081x over previous
#include <cuda_runtime.h>
#include <cuda_bf16.h>
#include <math.h>
#include <stdint.h>

#define N 8192
#define D 1024
#define BM 128
#define BN 128
#define BK 32
#define KSTEPS (D / BK)   // 32
#define NB (N / BM)       // 64 block-rows
#define NTRI (NB * (NB + 1) / 2)  // 2080 upper-tri blocks

// Scratch (__device__ globals: allocation-free rule)
__device__ __nv_bfloat16 g_xnb[(size_t)N * D];   // normalized rows, bf16, 16 MB
__device__ float g_top[N];
__device__ float g_bot[N];
__device__ int   g_lab[N];

// ------------------------------ PTX helpers -------------------------------
__device__ __forceinline__ uint32_t smem_u32(const void* p) {
    uint32_t a;
    asm("{ .reg .u64 t; cvta.to.shared.u64 t, %1; cvt.u32.u64 %0, t; }"
        : "=r"(a) : "l"(p));
    return a;
}
#define CPA(dst, src) \
    asm volatile("cp.async.cg.shared.global [%0], [%1], 16;" :: "r"(dst), "l"(src) : "memory")
#define CPA_COMMIT() asm volatile("cp.async.commit_group;" ::: "memory")
#define CPA_WAIT0()  asm volatile("cp.async.wait_group 0;" ::: "memory")
#define CPA_WAIT1()  asm volatile("cp.async.wait_group 1;" ::: "memory")

#define LDX4(r, a) \
    asm volatile("ldmatrix.sync.aligned.m8n8.x4.shared.b16 {%0,%1,%2,%3}, [%4];" \
        : "=r"((r)[0]), "=r"((r)[1]), "=r"((r)[2]), "=r"((r)[3]) : "r"(a))

__device__ __forceinline__ void mma16816(float* d, const uint32_t* a, const uint32_t* b) {
    asm volatile(
        "mma.sync.aligned.m16n8k16.row.col.f32.bf16.bf16.f32 "
        "{%0,%1,%2,%3}, {%4,%5,%6,%7}, {%8,%9}, {%0,%1,%2,%3};"
        : "+f"(d[0]), "+f"(d[1]), "+f"(d[2]), "+f"(d[3])
        : "r"(a[0]), "r"(a[1]), "r"(a[2]), "r"(a[3]), "r"(b[0]), "r"(b[1]));
}

// ---------------------------------------------------------------------------
// Row normalization -> bf16 unit rows; zero top/bot accumulators.
// ---------------------------------------------------------------------------
__global__ void normalize_kernel(const float* __restrict__ x) {
    int row = blockIdx.x;
    int t = threadIdx.x;
    const float4* xr = reinterpret_cast<const float4*>(x + (size_t)row * D);
    float4 v = xr[t];
    float ss = v.x * v.x + v.y * v.y + v.z * v.z + v.w * v.w;
    #pragma unroll
    for (int o = 16; o; o >>= 1) ss += __shfl_xor_sync(0xffffffffu, ss, o);
    __shared__ float sred[8];
    int lane = t & 31, w = t >> 5;
    if (lane == 0) sred[w] = ss;
    __syncthreads();
    if (t < 32) {
        float s2 = (t < 8) ? sred[t] : 0.0f;
        #pragma unroll
        for (int o = 4; o; o >>= 1) s2 += __shfl_xor_sync(0xffffffffu, s2, o);
        if (t == 0) sred[0] = s2;
    }
    __syncthreads();
    float inv = 1.0f / fmaxf(sqrtf(sred[0]), 1e-8f);
    __nv_bfloat162* dst = reinterpret_cast<__nv_bfloat162*>(g_xnb + (size_t)row * D);
    dst[2 * t + 0] = __floats2bfloat162_rn(v.x * inv, v.y * inv);
    dst[2 * t + 1] = __floats2bfloat162_rn(v.z * inv, v.w * inv);
    if (t == 0) { g_top[row] = 0.0f; g_bot[row] = 0.0f; }
}

// ---------------------------------------------------------------------------
// Label conversion with int64/int32 auto-detection (labels in [0,10)).
// ---------------------------------------------------------------------------
__global__ void labels_kernel(const int* __restrict__ y32) {
    __shared__ int odd_nonzero;
    int t = threadIdx.x;
    if (t == 0) odd_nonzero = 0;
    __syncthreads();
    if (t < 256 && y32[2 * t + 1] != 0) odd_nonzero = 1;
    __syncthreads();
    bool is64 = (odd_nonzero == 0);
    int i = blockIdx.x * blockDim.x + t;
    if (i < N) g_lab[i] = is64 ? y32[2 * i] : y32[i];
}

// ---------------------------------------------------------------------------
// HMMA fused sim-GEMM + SNNL epilogue, upper-triangular blocks only.
// 256 threads (8 warps: 2 M x 4 N). Off-diagonal CTAs scatter both row sums
// (for i) and column sums (for j), exploiting f(i,j) = f(j,i).
// ---------------------------------------------------------------------------
__global__ void __launch_bounds__(256, 2)
snnl_hmma(const float* __restrict__ Tptr) {
    __shared__ __align__(1024) __nv_bfloat16 sA[2][BM * BK];
    __shared__ __align__(1024) __nv_bfloat16 sB[2][BN * BK];

    const int tid = threadIdx.x;
    const int wid = tid >> 5;
    const int lane = tid & 31;

    // triangular decode: blockIdx.x -> (bi, bj), bi <= bj
    int t = blockIdx.x, bi = 0, rem = NB;
    while (t >= rem) { t -= rem; bi++; rem--; }
    const int bj = bi + t;
    const bool diag = (bi == bj);
    const int i0 = bi * BM;
    const int j0 = bj * BN;

    const int wm = (wid >> 2) * 64;   // 0 / 64
    const int wn = (wid & 3) * 32;    // 0 / 32 / 64 / 96

    uint32_t aBase[2] = { smem_u32(&sA[0][0]), smem_u32(&sA[1][0]) };
    uint32_t bBase[2] = { smem_u32(&sB[0][0]), smem_u32(&sB[1][0]) };

    // loader mapping: 256 threads cover 64 rows x 4 x 16B chunks; two halves
    const int lrow = tid >> 2;
    const int lch  = tid & 3;
    const uint32_t loff = lrow * 64 + ((lch ^ ((lrow >> 1) & 3)) << 4);
    const __nv_bfloat16* Ag = g_xnb + (size_t)(i0 + lrow) * D + lch * 8;
    const __nv_bfloat16* Bg = g_xnb + (size_t)(j0 + lrow) * D + lch * 8;

    // ldmatrix per-lane address components
    uint32_t aoff[4], asw[4];
    #pragma unroll
    for (int mt = 0; mt < 4; mt++) {
        int r = wm + mt * 16 + ((lane >> 3) & 1) * 8 + (lane & 7);
        aoff[mt] = r * 64;
        asw[mt] = (r >> 1) & 3;
    }
    uint32_t boff[2], bsw[2];
    #pragma unroll
    for (int bt = 0; bt < 2; bt++) {
        int r = wn + bt * 16 + (lane >> 4) * 8 + (lane & 7);
        boff[bt] = r * 64;
        bsw[bt] = (r >> 1) & 3;
    }

    float acc[4][4][4];
    #pragma unroll
    for (int a = 0; a < 4; a++)
        #pragma unroll
        for (int b = 0; b < 4; b++)
            #pragma unroll
            for (int c = 0; c < 4; c++) acc[a][b][c] = 0.0f;

    CPA(aBase[0] + loff,        Ag);
    CPA(aBase[0] + loff + 4096, Ag + (size_t)64 * D);
    CPA(bBase[0] + loff,        Bg);
    CPA(bBase[0] + loff + 4096, Bg + (size_t)64 * D);
    CPA_COMMIT();

    for (int kc = 0; kc < KSTEPS; kc++) {
        const int b = kc & 1;
        if (kc + 1 < KSTEPS) {
            const __nv_bfloat16* An = Ag + (kc + 1) * BK;
            const __nv_bfloat16* Bn = Bg + (kc + 1) * BK;
            CPA(aBase[1 - b] + loff,        An);
            CPA(aBase[1 - b] + loff + 4096, An + (size_t)64 * D);
            CPA(bBase[1 - b] + loff,        Bn);
            CPA(bBase[1 - b] + loff + 4096, Bn + (size_t)64 * D);
            CPA_COMMIT();
            CPA_WAIT1();
        } else {
            CPA_WAIT0();
        }
        __syncthreads();

        #pragma unroll
        for (int ks = 0; ks < 2; ks++) {
            uint32_t af[4][4], bf[2][4];
            const uint32_t ca = 2 * ks + (lane >> 4);
            const uint32_t cb = 2 * ks + ((lane >> 3) & 1);
            #pragma unroll
            for (int mt = 0; mt < 4; mt++)
                LDX4(af[mt], aBase[b] + aoff[mt] + ((ca ^ asw[mt]) << 4));
            #pragma unroll
            for (int bt = 0; bt < 2; bt++)
                LDX4(bf[bt], bBase[b] + boff[bt] + ((cb ^ bsw[bt]) << 4));
            #pragma unroll
            for (int mt = 0; mt < 4; mt++)
                #pragma unroll
                for (int nt = 0; nt < 4; nt++)
                    mma16816(acc[mt][nt], af[mt], &bf[nt >> 1][(nt & 1) * 2]);
        }
        __syncthreads();
    }

    // ---------------- epilogue ----------------
    const float invT = 1.0f / Tptr[0];
    float* rowsum = reinterpret_cast<float*>(&sA[0][0]);   // 128 x {top,bot}
    float* colsum = rowsum + 256;                          // 128 x {top,bot}
    rowsum[tid] = 0.0f;
    colsum[tid] = 0.0f;
    __syncthreads();

    const int g = lane >> 2, tig = lane & 3;
    int yj[4][2];
    #pragma unroll
    for (int nt = 0; nt < 4; nt++) {
        int j = j0 + wn + nt * 8 + 2 * tig;
        yj[nt][0] = g_lab[j];
        yj[nt][1] = g_lab[j + 1];
    }

    float ct[4][2] = {}, cb2[4][2] = {};   // per-thread column partials

    #pragma unroll
    for (int mt = 0; mt < 4; mt++) {
        #pragma unroll
        for (int h = 0; h < 2; h++) {
            const int li = wm + mt * 16 + h * 8 + g;
            const int i = i0 + li;
            const int yi = g_lab[i];
            float ts = 0.0f, bs = 0.0f;
            #pragma unroll
            for (int nt = 0; nt < 4; nt++) {
                float d0 = acc[mt][nt][h * 2 + 0];
                float d1 = acc[mt][nt][h * 2 + 1];
                int j = j0 + wn + nt * 8 + 2 * tig;
                float f0 = __expf((d0 - 1.0f) * invT);
                float f1 = __expf((d1 - 1.0f) * invT);
                if (i == j) f0 = 0.0f;
                if (i == j + 1) f1 = 0.0f;
                bs += f0 + f1;
                cb2[nt][0] += f0;
                cb2[nt][1] += f1;
                if (yi == yj[nt][0]) { ts += f0; ct[nt][0] += f0; }
                if (yi == yj[nt][1]) { ts += f1; ct[nt][1] += f1; }
            }
            ts += __shfl_xor_sync(0xffffffffu, ts, 1);
            ts += __shfl_xor_sync(0xffffffffu, ts, 2);
            bs += __shfl_xor_sync(0xffffffffu, bs, 1);
            bs += __shfl_xor_sync(0xffffffffu, bs, 2);
            if (tig == 0) {
                atomicAdd(&rowsum[li * 2 + 0], ts);
                atomicAdd(&rowsum[li * 2 + 1], bs);
            }
        }
    }

    if (!diag) {
        // column reduce across the 8 g-lanes (same tig): shfl offsets 4, 8, 16
        #pragma unroll
        for (int nt = 0; nt < 4; nt++) {
            #pragma unroll
            for (int c = 0; c < 2; c++) {
                float vt = ct[nt][c], vb = cb2[nt][c];
                #pragma unroll
                for (int o = 4; o < 32; o <<= 1) {
                    vt += __shfl_xor_sync(0xffffffffu, vt, o);
                    vb += __shfl_xor_sync(0xffffffffu, vb, o);
                }
                if (g == 0) {
                    int lj = wn + nt * 8 + 2 * tig + c;
                    atomicAdd(&colsum[lj * 2 + 0], vt);
                    atomicAdd(&colsum[lj * 2 + 1], vb);
                }
            }
        }
    }

    __syncthreads();
    if (tid < BM) {
        atomicAdd(&g_top[i0 + tid], rowsum[tid * 2 + 0]);
        atomicAdd(&g_bot[i0 + tid], rowsum[tid * 2 + 1]);
        if (!diag) {
            atomicAdd(&g_top[j0 + tid], colsum[tid * 2 + 0]);
            atomicAdd(&g_bot[j0 + tid], colsum[tid * 2 + 1]);
        }
    }
}

// ---------------------------------------------------------------------------
// Final loss: -mean(log((top + 1e-9) / bot))
// ---------------------------------------------------------------------------
__global__ void loss_kernel(float* __restrict__ out) {
    int t = threadIdx.x;
    float s = 0.0f;
    for (int i = t; i < N; i += 256)
        s += __logf((g_top[i] + 1e-9f) / g_bot[i]);
    #pragma unroll
    for (int o = 16; o; o >>= 1) s += __shfl_xor_sync(0xffffffffu, s, o);
    __shared__ float sred[8];
    int lane = t & 31, w = t >> 5;
    if (lane == 0) sred[w] = s;
    __syncthreads();
    if (t < 32) {
        float s2 = (t < 8) ? sred[t] : 0.0f;
        #pragma unroll
        for (int o = 4; o; o >>= 1) s2 += __shfl_xor_sync(0xffffffffu, s2, o);
        if (t == 0) out[0] = -s2 / (float)N;
    }
}

extern "C" void kernel_launch(void* const* d_in, const int* in_sizes, int n_in,
                              void* d_out, int out_size) {
    const float* x = (const float*)d_in[0];
    const int*   y = (const int*)d_in[1];   // int32 view; layout auto-detected
    const float* T = (const float*)d_in[2];
    float* out = (float*)d_out;

    normalize_kernel<<<N, 256>>>(x);
    labels_kernel<<<N / 256, 256>>>(y);
    snnl_hmma<<<NTRI, 256>>>(T);
    loss_kernel<<<1, 256>>>(out);
}

// round 5
// speedup vs baseline: 19.2513x; 1.0594x over previous
#include <cuda_runtime.h>
#include <cuda_bf16.h>
#include <math.h>
#include <stdint.h>

#define N 8192
#define D 1024
#define BM 128
#define BN 128
#define BK 64             // fp8 elems per k-chunk (64 bytes per row-chunk)
#define KSTEPS (D / BK)   // 16
#define NB (N / BM)       // 64 block-rows
#define NTRI (NB * (NB + 1) / 2)  // 2080 upper-tri blocks

// Scratch (__device__ globals: allocation-free rule)
__device__ uint8_t g_xq[(size_t)N * D];   // normalized rows, e4m3, 8 MB
__device__ float g_top[N];
__device__ float g_bot[N];
__device__ int   g_lab[N];
__device__ float g_loss;

// ------------------------------ PTX helpers -------------------------------
__device__ __forceinline__ uint32_t smem_u32(const void* p) {
    uint32_t a;
    asm("{ .reg .u64 t; cvta.to.shared.u64 t, %1; cvt.u32.u64 %0, t; }"
        : "=r"(a) : "l"(p));
    return a;
}
#define CPA(dst, src) \
    asm volatile("cp.async.cg.shared.global [%0], [%1], 16;" :: "r"(dst), "l"(src) : "memory")
#define CPA_COMMIT() asm volatile("cp.async.commit_group;" ::: "memory")
#define CPA_WAIT0()  asm volatile("cp.async.wait_group 0;" ::: "memory")

#define LDX4(r, a) \
    asm volatile("ldmatrix.sync.aligned.m8n8.x4.shared.b16 {%0,%1,%2,%3}, [%4];" \
        : "=r"((r)[0]), "=r"((r)[1]), "=r"((r)[2]), "=r"((r)[3]) : "r"(a))

__device__ __forceinline__ void mma_fp8(float* d, const uint32_t* a, const uint32_t* b) {
    asm volatile(
        "mma.sync.aligned.m16n8k32.row.col.f32.e4m3.e4m3.f32 "
        "{%0,%1,%2,%3}, {%4,%5,%6,%7}, {%8,%9}, {%0,%1,%2,%3};"
        : "+f"(d[0]), "+f"(d[1]), "+f"(d[2]), "+f"(d[3])
        : "r"(a[0]), "r"(a[1]), "r"(a[2]), "r"(a[3]), "r"(b[0]), "r"(b[1]));
}

// ---------------------------------------------------------------------------
// Row normalization -> e4m3 unit rows; zero top/bot accumulators.
// ---------------------------------------------------------------------------
__global__ void normalize_kernel(const float* __restrict__ x) {
    int row = blockIdx.x;
    int t = threadIdx.x;
    const float4* xr = reinterpret_cast<const float4*>(x + (size_t)row * D);
    float4 v = xr[t];
    float ss = v.x * v.x + v.y * v.y + v.z * v.z + v.w * v.w;
    #pragma unroll
    for (int o = 16; o; o >>= 1) ss += __shfl_xor_sync(0xffffffffu, ss, o);
    __shared__ float sred[8];
    int lane = t & 31, w = t >> 5;
    if (lane == 0) sred[w] = ss;
    __syncthreads();
    if (t < 32) {
        float s2 = (t < 8) ? sred[t] : 0.0f;
        #pragma unroll
        for (int o = 4; o; o >>= 1) s2 += __shfl_xor_sync(0xffffffffu, s2, o);
        if (t == 0) sred[0] = s2;
    }
    __syncthreads();
    float inv = 1.0f / fmaxf(sqrtf(sred[0]), 1e-8f);
    // pack 4 fp8 (e4m3), low byte = first element
    uint16_t h0, h1;
    asm("cvt.rn.satfinite.e4m3x2.f32 %0, %1, %2;" : "=h"(h0) : "f"(v.y * inv), "f"(v.x * inv));
    asm("cvt.rn.satfinite.e4m3x2.f32 %0, %1, %2;" : "=h"(h1) : "f"(v.w * inv), "f"(v.z * inv));
    reinterpret_cast<uint32_t*>(g_xq + (size_t)row * D)[t] =
        (uint32_t)h0 | ((uint32_t)h1 << 16);
    if (t == 0) { g_top[row] = 0.0f; g_bot[row] = 0.0f; }
}

// ---------------------------------------------------------------------------
// Label conversion with int64/int32 auto-detection (labels in [0,10)).
// Also zeroes the loss accumulator.
// ---------------------------------------------------------------------------
__global__ void labels_kernel(const int* __restrict__ y32) {
    __shared__ int odd_nonzero;
    int t = threadIdx.x;
    if (t == 0) odd_nonzero = 0;
    __syncthreads();
    if (t < 256 && y32[2 * t + 1] != 0) odd_nonzero = 1;
    __syncthreads();
    bool is64 = (odd_nonzero == 0);
    int i = blockIdx.x * blockDim.x + t;
    if (i < N) g_lab[i] = is64 ? y32[2 * i] : y32[i];
    if (i == 0) g_loss = 0.0f;
}

// ---------------------------------------------------------------------------
// FP8 MMA fused sim-GEMM + SNNL epilogue, upper-triangular blocks only.
// 256 threads (8 warps: 2 M x 4 N). Off-diagonal CTAs scatter both row sums
// (for i) and column sums (for j); diagonal CTAs reuse the A tile for B.
// smem rows: 64 B (64 fp8), 16B-chunk XOR swizzle on (row>>1)&3.
// ---------------------------------------------------------------------------
__global__ void __launch_bounds__(256, 2)
snnl_fp8(const float* __restrict__ Tptr) {
    __shared__ __align__(1024) uint8_t sA[2][BM * BK];
    __shared__ __align__(1024) uint8_t sB[2][BN * BK];

    const int tid = threadIdx.x;
    const int wid = tid >> 5;
    const int lane = tid & 31;

    // triangular decode: blockIdx.x -> (bi, bj), bi <= bj
    int t = blockIdx.x, bi = 0, rem = NB;
    while (t >= rem) { t -= rem; bi++; rem--; }
    const int bj = bi + t;
    const bool diag = (bi == bj);
    const int i0 = bi * BM;
    const int j0 = bj * BN;

    const int wm = (wid >> 2) * 64;   // 0 / 64
    const int wn = (wid & 3) * 32;    // 0 / 32 / 64 / 96

    uint32_t aBase[2] = { smem_u32(&sA[0][0]), smem_u32(&sA[1][0]) };
    uint32_t bBase[2] = { smem_u32(&sB[0][0]), smem_u32(&sB[1][0]) };
    if (diag) { bBase[0] = aBase[0]; bBase[1] = aBase[1]; }

    // loader mapping: 256 threads cover 64 rows x 4 x 16B chunks; two halves
    const int lrow = tid >> 2;
    const int lch  = tid & 3;
    const uint32_t loff = lrow * 64 + ((lch ^ ((lrow >> 1) & 3)) << 4);
    const uint8_t* Ag = g_xq + (size_t)(i0 + lrow) * D + lch * 16;
    const uint8_t* Bg = g_xq + (size_t)(j0 + lrow) * D + lch * 16;

    // ldmatrix per-lane address components
    uint32_t aoff[4], asw[4];
    #pragma unroll
    for (int mt = 0; mt < 4; mt++) {
        int r = wm + mt * 16 + ((lane >> 3) & 1) * 8 + (lane & 7);
        aoff[mt] = r * 64;
        asw[mt] = (r >> 1) & 3;
    }
    uint32_t boff[2], bsw[2];
    #pragma unroll
    for (int bt = 0; bt < 2; bt++) {
        int r = wn + bt * 16 + (lane >> 4) * 8 + (lane & 7);
        boff[bt] = r * 64;
        bsw[bt] = (r >> 1) & 3;
    }

    float acc[4][4][4];
    #pragma unroll
    for (int a = 0; a < 4; a++)
        #pragma unroll
        for (int b = 0; b < 4; b++)
            #pragma unroll
            for (int c = 0; c < 4; c++) acc[a][b][c] = 0.0f;

    // prologue: load chunk 0 into buffer 0
    CPA(aBase[0] + loff,        Ag);
    CPA(aBase[0] + loff + 4096, Ag + (size_t)64 * D);
    if (!diag) {
        CPA(bBase[0] + loff,        Bg);
        CPA(bBase[0] + loff + 4096, Bg + (size_t)64 * D);
    }
    CPA_COMMIT();

    for (int kc = 0; kc < KSTEPS; kc++) {
        const int b = kc & 1;
        CPA_WAIT0();           // buffer b data arrived
        __syncthreads();       // visible to all; everyone done reading 1-b
        if (kc + 1 < KSTEPS) {
            const uint8_t* An = Ag + (kc + 1) * BK;
            CPA(aBase[1 - b] + loff,        An);
            CPA(aBase[1 - b] + loff + 4096, An + (size_t)64 * D);
            if (!diag) {
                const uint8_t* Bn = Bg + (kc + 1) * BK;
                CPA(bBase[1 - b] + loff,        Bn);
                CPA(bBase[1 - b] + loff + 4096, Bn + (size_t)64 * D);
            }
            CPA_COMMIT();
        }

        #pragma unroll
        for (int ks = 0; ks < 2; ks++) {
            uint32_t af[4][4], bf[2][4];
            const uint32_t ca = 2 * ks + (lane >> 4);
            const uint32_t cb = 2 * ks + ((lane >> 3) & 1);
            #pragma unroll
            for (int mt = 0; mt < 4; mt++)
                LDX4(af[mt], aBase[b] + aoff[mt] + ((ca ^ asw[mt]) << 4));
            #pragma unroll
            for (int bt = 0; bt < 2; bt++)
                LDX4(bf[bt], bBase[b] + boff[bt] + ((cb ^ bsw[bt]) << 4));
            #pragma unroll
            for (int mt = 0; mt < 4; mt++)
                #pragma unroll
                for (int nt = 0; nt < 4; nt++)
                    mma_fp8(acc[mt][nt], af[mt], &bf[nt >> 1][(nt & 1) * 2]);
        }
    }
    __syncthreads();   // all compute done before reusing sA as accumulators

    // ---------------- epilogue ----------------
    const float invT = 1.0f / Tptr[0];
    float* rowsum = reinterpret_cast<float*>(&sA[0][0]);   // 128 x {top,bot}
    float* colsum = rowsum + 256;                          // 128 x {top,bot}
    rowsum[tid] = 0.0f;
    colsum[tid] = 0.0f;
    __syncthreads();

    const int g = lane >> 2, tig = lane & 3;
    int yj[4][2];
    #pragma unroll
    for (int nt = 0; nt < 4; nt++) {
        int j = j0 + wn + nt * 8 + 2 * tig;
        yj[nt][0] = g_lab[j];
        yj[nt][1] = g_lab[j + 1];
    }

    float ct[4][2] = {}, cb2[4][2] = {};   // per-thread column partials

    #pragma unroll
    for (int mt = 0; mt < 4; mt++) {
        #pragma unroll
        for (int h = 0; h < 2; h++) {
            const int li = wm + mt * 16 + h * 8 + g;
            const int i = i0 + li;
            const int yi = g_lab[i];
            float ts = 0.0f, bs = 0.0f;
            #pragma unroll
            for (int nt = 0; nt < 4; nt++) {
                float d0 = acc[mt][nt][h * 2 + 0];
                float d1 = acc[mt][nt][h * 2 + 1];
                int j = j0 + wn + nt * 8 + 2 * tig;
                float f0 = __expf((d0 - 1.0f) * invT);
                float f1 = __expf((d1 - 1.0f) * invT);
                if (i == j) f0 = 0.0f;
                if (i == j + 1) f1 = 0.0f;
                bs += f0 + f1;
                cb2[nt][0] += f0;
                cb2[nt][1] += f1;
                if (yi == yj[nt][0]) { ts += f0; ct[nt][0] += f0; }
                if (yi == yj[nt][1]) { ts += f1; ct[nt][1] += f1; }
            }
            ts += __shfl_xor_sync(0xffffffffu, ts, 1);
            ts += __shfl_xor_sync(0xffffffffu, ts, 2);
            bs += __shfl_xor_sync(0xffffffffu, bs, 1);
            bs += __shfl_xor_sync(0xffffffffu, bs, 2);
            if (tig == 0) {
                atomicAdd(&rowsum[li * 2 + 0], ts);
                atomicAdd(&rowsum[li * 2 + 1], bs);
            }
        }
    }

    if (!diag) {
        #pragma unroll
        for (int nt = 0; nt < 4; nt++) {
            #pragma unroll
            for (int c = 0; c < 2; c++) {
                float vt = ct[nt][c], vb = cb2[nt][c];
                #pragma unroll
                for (int o = 4; o < 32; o <<= 1) {
                    vt += __shfl_xor_sync(0xffffffffu, vt, o);
                    vb += __shfl_xor_sync(0xffffffffu, vb, o);
                }
                if (g == 0) {
                    int lj = wn + nt * 8 + 2 * tig + c;
                    atomicAdd(&colsum[lj * 2 + 0], vt);
                    atomicAdd(&colsum[lj * 2 + 1], vb);
                }
            }
        }
    }

    __syncthreads();
    if (tid < BM) {
        atomicAdd(&g_top[i0 + tid], rowsum[tid * 2 + 0]);
        atomicAdd(&g_bot[i0 + tid], rowsum[tid * 2 + 1]);
        if (!diag) {
            atomicAdd(&g_top[j0 + tid], colsum[tid * 2 + 0]);
            atomicAdd(&g_bot[j0 + tid], colsum[tid * 2 + 1]);
        }
    }
}

// ---------------------------------------------------------------------------
// Loss: stage 1 — 32 blocks reduce log terms into g_loss.
// ---------------------------------------------------------------------------
__global__ void loss_part(void) {
    int i = blockIdx.x * 256 + threadIdx.x;
    float s = __logf((g_top[i] + 1e-9f) / g_bot[i]);
    #pragma unroll
    for (int o = 16; o; o >>= 1) s += __shfl_xor_sync(0xffffffffu, s, o);
    __shared__ float sred[8];
    int lane = threadIdx.x & 31, w = threadIdx.x >> 5;
    if (lane == 0) sred[w] = s;
    __syncthreads();
    if (threadIdx.x < 32) {
        float s2 = (threadIdx.x < 8) ? sred[threadIdx.x] : 0.0f;
        #pragma unroll
        for (int o = 4; o; o >>= 1) s2 += __shfl_xor_sync(0xffffffffu, s2, o);
        if (threadIdx.x == 0) atomicAdd(&g_loss, s2);
    }
}

// stage 2 — finalize
__global__ void loss_fin(float* __restrict__ out) {
    out[0] = -g_loss / (float)N;
}

extern "C" void kernel_launch(void* const* d_in, const int* in_sizes, int n_in,
                              void* d_out, int out_size) {
    const float* x = (const float*)d_in[0];
    const int*   y = (const int*)d_in[1];   // int32 view; layout auto-detected
    const float* T = (const float*)d_in[2];
    float* out = (float*)d_out;

    normalize_kernel<<<N, 256>>>(x);
    labels_kernel<<<N / 256, 256>>>(y);
    snnl_fp8<<<NTRI, 256>>>(T);
    loss_part<<<N / 256, 256>>>();
    loss_fin<<<1, 1>>>(out);
}